// round 16
// baseline (speedup 1.0000x reference)
#include <cuda_runtime.h>
#include <cuda_fp16.h>
#include <cstdint>

#define MAX_NODES 100000
#define UNITS 128

// ---------------------------------------------------------------------------
// Scratch (no cudaMalloc allowed)
// ---------------------------------------------------------------------------
__device__ __align__(16) float g_h[(size_t)MAX_NODES * UNITS];       // 51.2 MB
__device__ __align__(16) unsigned short g_xh[(size_t)MAX_NODES * UNITS]; // 25.6 MB fp16 X
__device__ int   g_row_ptr[MAX_NODES + 1];
__device__ int   g_idx64;
// W as fp16, stored as B[n][k] = W[k][n], row-major [128][128]
__device__ __align__(16) unsigned short g_whi[128 * 128];

__device__ __forceinline__ uint32_t smem_u32(const void* p) {
    uint32_t a;
    asm("{ .reg .u64 t; cvta.to.shared.u64 t, %1; cvt.u32.u64 %0, t; }"
        : "=r"(a) : "l"(p));
    return a;
}

__device__ __forceinline__ uint32_t h2_as_u32(__half2 h) {
    union { __half2 h; uint32_t u; } cvt;
    cvt.h = h;
    return cvt.u;
}

template <int IS64>
__device__ __forceinline__ int load_idx(const void* p, int i) {
    if (IS64) return (int)__ldg(((const long long*)p) + i);
    return __ldg(((const int*)p) + i);
}

// ---------------------------------------------------------------------------
// prep: W -> fp16 image B[n][k]  +  index-dtype probe.
// ---------------------------------------------------------------------------
__global__ void prep_kernel(const float* __restrict__ W, const int* __restrict__ ec) {
    if (blockIdx.x == 0 && threadIdx.x == 0) {
        int nz = 0;
        #pragma unroll
        for (int i = 1; i < 64; i += 2) nz += (ec[i] != 0);
        g_idx64 = (nz == 0) ? 1 : 0;
    }
    int i = blockIdx.x * blockDim.x + threadIdx.x;
    if (i >= 128 * 128) return;
    int n = i >> 7, k = i & 127;
    float w = __ldg(W + (size_t)k * 128 + n);
    g_whi[n * 128 + k] = __half_as_ushort(__float2half_rn(w));
}

// ---------------------------------------------------------------------------
// mid: fused  (a) CSR row_ptr edge-diff scatter  (b) X -> fp16 conversion.
// ---------------------------------------------------------------------------
template <int IS64>
__device__ __forceinline__ void rowptr_part(const void* er, int E, int M, int bid) {
    int i = bid * blockDim.x + threadIdx.x;
    if (i > E) return;
    if (i == E) {
        int last = load_idx<IS64>(er, E - 1);
        for (int r = last + 1; r <= M; r++) g_row_ptr[r] = E;
        return;
    }
    int r1 = load_idx<IS64>(er, i);
    int r0 = (i == 0) ? -1 : load_idx<IS64>(er, i - 1);
    for (int r = r0 + 1; r <= r1; r++) g_row_ptr[r] = i;
}

__global__ void mid_kernel(const void* __restrict__ er, int E, int M,
                           const float* __restrict__ X, int rb, int items)
{
    int bid = blockIdx.x;
    if (bid < rb) {
        if (g_idx64) rowptr_part<1>(er, E, M, bid);
        else         rowptr_part<0>(er, E, M, bid);
        return;
    }
    int j = (bid - rb) * blockDim.x + threadIdx.x;
    if (j >= items) return;
    const float4* src = (const float4*)X + (size_t)j * 2;
    float4 a = __ldg(src);
    float4 b = __ldg(src + 1);
    uint4 o;
    o.x = h2_as_u32(__floats2half2_rn(a.x, a.y));
    o.y = h2_as_u32(__floats2half2_rn(a.z, a.w));
    o.z = h2_as_u32(__floats2half2_rn(b.x, b.y));
    o.w = h2_as_u32(__floats2half2_rn(b.z, b.w));
    ((uint4*)g_xh)[j] = o;
}

// ---------------------------------------------------------------------------
// HMMA GEMM: g_h[M,128] = Xh[M,128] @ W[128,128]   (both already fp16)
// cp.async staging, fp32 accum, mma.sync.m16n8k16, 3 CTA/SM.
// ---------------------------------------------------------------------------
#define LDS_STRIDE 136
#define TILE_BYTES (128 * LDS_STRIDE * 2)
#define SM_XHI 0
#define SM_WHI (SM_XHI + TILE_BYTES)
#define SM_TOTAL (SM_WHI + TILE_BYTES)

__device__ __forceinline__ void cp_async16(uint32_t dst, const void* src) {
    asm volatile("cp.async.ca.shared.global [%0], [%1], 16;"
                 :: "r"(dst), "l"(__cvta_generic_to_global(src)) : "memory");
}
__device__ __forceinline__ void cp_async_wait_all() {
    asm volatile("cp.async.commit_group;\n\tcp.async.wait_group 0;" ::: "memory");
}
__device__ __forceinline__ void ldsm_x4(uint32_t* r, uint32_t addr) {
    asm volatile("ldmatrix.sync.aligned.m8n8.x4.shared.b16 {%0,%1,%2,%3}, [%4];"
                 : "=r"(r[0]), "=r"(r[1]), "=r"(r[2]), "=r"(r[3]) : "r"(addr));
}
__device__ __forceinline__ void mma_fp16(float* c, const uint32_t* a, const uint32_t* b) {
    asm volatile(
        "mma.sync.aligned.m16n8k16.row.col.f32.f16.f16.f32 "
        "{%0,%1,%2,%3}, {%4,%5,%6,%7}, {%8,%9}, {%0,%1,%2,%3};"
        : "+f"(c[0]), "+f"(c[1]), "+f"(c[2]), "+f"(c[3])
        : "r"(a[0]), "r"(a[1]), "r"(a[2]), "r"(a[3]), "r"(b[0]), "r"(b[1]));
}

__global__ __launch_bounds__(256, 3)
void gemm_hmma_kernel(int M)
{
    extern __shared__ char smem[];
    const uint32_t sb = smem_u32(smem);
    const int tid = threadIdx.x;
    const int wid = tid >> 5, lane = tid & 31;
    const int m0 = blockIdx.x * 128;
    const int mrows = min(128, M - m0);

    {
        #pragma unroll
        for (int i = 0; i < 8; i++) {
            int cid = tid + i * 256;
            int r = cid >> 4, j = cid & 15;
            if (r < mrows)
                cp_async16(sb + SM_XHI + r * (LDS_STRIDE * 2) + j * 16,
                           g_xh + (size_t)(m0 + r) * 128 + j * 8);
        }
        #pragma unroll
        for (int i = 0; i < 8; i++) {
            int cid = tid + i * 256;
            int r = cid >> 4, j = cid & 15;
            cp_async16(sb + SM_WHI + r * (LDS_STRIDE * 2) + j * 16,
                       g_whi + r * 128 + j * 8);
        }
        if (mrows < 128) {
            for (int cid = tid; cid < 2048; cid += 256) {
                int r = cid >> 4, j = cid & 15;
                if (r >= mrows)
                    *(uint4*)(smem + SM_XHI + r * (LDS_STRIDE * 2) + j * 16) =
                        make_uint4(0, 0, 0, 0);
            }
        }
        cp_async_wait_all();
    }
    __syncthreads();

    const int warp_m = wid & 3, warp_n = wid >> 2;
    const int mb = warp_m * 32;
    const int nb = warp_n * 64;

    float acc[2][8][4];
    #pragma unroll
    for (int i = 0; i < 2; i++)
        #pragma unroll
        for (int j = 0; j < 8; j++)
            #pragma unroll
            for (int q = 0; q < 4; q++) acc[i][j][q] = 0.0f;

    const int g = lane >> 3, lr = lane & 7;

    #pragma unroll
    for (int kk = 0; kk < 8; kk++) {
        const int k0 = kk * 16;
        uint32_t ahi[2][4];
        #pragma unroll
        for (int mt = 0; mt < 2; mt++) {
            uint32_t off = (uint32_t)(mb + mt * 16 + (g & 1) * 8 + lr) * (LDS_STRIDE * 2)
                         + (uint32_t)(k0 + (g >> 1) * 8) * 2;
            ldsm_x4(ahi[mt], sb + SM_XHI + off);
        }
        #pragma unroll
        for (int bt = 0; bt < 4; bt++) {
            uint32_t off = (uint32_t)(nb + bt * 16 + (g >> 1) * 8 + lr) * (LDS_STRIDE * 2)
                         + (uint32_t)(k0 + (g & 1) * 8) * 2;
            uint32_t bhi[4];
            ldsm_x4(bhi, sb + SM_WHI + off);
            #pragma unroll
            for (int mt = 0; mt < 2; mt++)
                #pragma unroll
                for (int nt = 0; nt < 2; nt++)
                    mma_fp16(acc[mt][bt * 2 + nt], ahi[mt], bhi + nt * 2);
        }
    }

    const int er = lane >> 2, ec2 = (lane & 3) * 2;
    #pragma unroll
    for (int mt = 0; mt < 2; mt++) {
        #pragma unroll
        for (int j = 0; j < 8; j++) {
            int n = nb + j * 8 + ec2;
            int m_lo = m0 + mb + mt * 16 + er;
            int m_hi = m_lo + 8;
            if (m_lo < M)
                *(float2*)(g_h + (size_t)m_lo * 128 + n) =
                    make_float2(acc[mt][j][0], acc[mt][j][1]);
            if (m_hi < M)
                *(float2*)(g_h + (size_t)m_hi * 128 + n) =
                    make_float2(acc[mt][j][2], acc[mt][j][3]);
        }
    }
}

// ---------------------------------------------------------------------------
// SpMM + bias + sigmoid: one warp per row, float4 column slice per lane.
// ec/ev loaded COOPERATIVELY (lanes 0-7: indices, lanes 8-15: values; 2
// L1tex wavefronts instead of 16 per 8 edges) and distributed via shfl.
// ---------------------------------------------------------------------------
template <int IS64>
__device__ __forceinline__ float coop_load_cv(const void* ec, const float* ev,
                                              int base, int lane, int span)
{
    // lanes [0, span): index bits of edge base+lane
    // lanes [span, 2*span): value of edge base+lane-span
    float cv = 0.0f;
    if (lane < span) {
        if (IS64) cv = __int_as_float(__ldg((const int*)ec + 2 * (base + lane)));
        else      cv = __int_as_float(__ldg((const int*)ec + base + lane));
    } else if (lane < 2 * span) {
        cv = __ldg(ev + base + lane - span);
    }
    return cv;
}

template <int IS64>
__device__ __forceinline__ void spmm_body(
    const void* ec, const float* ev, const float* bias, float* out, int M)
{
    int row = blockIdx.x * 8 + (threadIdx.x >> 5);
    if (row >= M) return;
    int lane = threadIdx.x & 31;

    int s = __ldg(&g_row_ptr[row]);
    int e = __ldg(&g_row_ptr[row + 1]);

    const float4* hp = (const float4*)g_h;
    float4 acc = make_float4(0, 0, 0, 0);

    int i = s;
    for (; i + 8 <= e; i += 8) {
        float cv = coop_load_cv<IS64>(ec, ev, i, lane, 8);
        int   c[8];
        float v[8];
        #pragma unroll
        for (int q = 0; q < 8; q++) {
            c[q] = __float_as_int(__shfl_sync(0xffffffffu, cv, q));
            v[q] = __shfl_sync(0xffffffffu, cv, 8 + q);
        }
        float4 h[8];
        #pragma unroll
        for (int q = 0; q < 8; q++) h[q] = hp[(size_t)c[q] * 32 + lane];
        #pragma unroll
        for (int q = 0; q < 8; q++) {
            acc.x = fmaf(v[q], h[q].x, acc.x);
            acc.y = fmaf(v[q], h[q].y, acc.y);
            acc.z = fmaf(v[q], h[q].z, acc.z);
            acc.w = fmaf(v[q], h[q].w, acc.w);
        }
    }
    if (i + 4 <= e) {
        float cv = coop_load_cv<IS64>(ec, ev, i, lane, 4);
        int   c[4];
        float v[4];
        #pragma unroll
        for (int q = 0; q < 4; q++) {
            c[q] = __float_as_int(__shfl_sync(0xffffffffu, cv, q));
            v[q] = __shfl_sync(0xffffffffu, cv, 4 + q);
        }
        float4 h[4];
        #pragma unroll
        for (int q = 0; q < 4; q++) h[q] = hp[(size_t)c[q] * 32 + lane];
        #pragma unroll
        for (int q = 0; q < 4; q++) {
            acc.x = fmaf(v[q], h[q].x, acc.x);
            acc.y = fmaf(v[q], h[q].y, acc.y);
            acc.z = fmaf(v[q], h[q].z, acc.z);
            acc.w = fmaf(v[q], h[q].w, acc.w);
        }
        i += 4;
    }
    for (; i < e; i++) {
        int c0 = load_idx<IS64>(ec, i);
        float v0 = __ldg(ev + i);
        float4 h0 = hp[(size_t)c0 * 32 + lane];
        acc.x = fmaf(v0, h0.x, acc.x); acc.y = fmaf(v0, h0.y, acc.y);
        acc.z = fmaf(v0, h0.z, acc.z); acc.w = fmaf(v0, h0.w, acc.w);
    }

    float4 b = __ldg(((const float4*)bias) + lane);
    float4 r;
    r.x = 1.0f / (1.0f + __expf(-(acc.x + b.x)));
    r.y = 1.0f / (1.0f + __expf(-(acc.y + b.y)));
    r.z = 1.0f / (1.0f + __expf(-(acc.z + b.z)));
    r.w = 1.0f / (1.0f + __expf(-(acc.w + b.w)));
    ((float4*)out)[(size_t)row * 32 + lane] = r;
}

__global__ __launch_bounds__(256) void spmm_kernel(
    const void* __restrict__ ec, const float* __restrict__ ev,
    const float* __restrict__ bias, float* __restrict__ out, int M)
{
    if (g_idx64) spmm_body<1>(ec, ev, bias, out, M);
    else         spmm_body<0>(ec, ev, bias, out, M);
}

// ---------------------------------------------------------------------------
// Launch. Inputs: X, edge_row, edge_col, edge_val, weight, bias
// ---------------------------------------------------------------------------
extern "C" void kernel_launch(void* const* d_in, const int* in_sizes, int n_in,
                              void* d_out, int out_size) {
    const float* X    = (const float*)d_in[0];
    const void*  er   = d_in[1];
    const void*  ec   = d_in[2];
    const float* ev   = (const float*)d_in[3];
    const float* W    = (const float*)d_in[4];
    const float* bias = (const float*)d_in[5];
    float* out = (float*)d_out;

    int M = in_sizes[0] / UNITS;     // 100000
    int E = in_sizes[2];             // 1600000

    static int smem_set = 0;
    if (!smem_set) {
        cudaFuncSetAttribute(gemm_hmma_kernel,
                             cudaFuncAttributeMaxDynamicSharedMemorySize, SM_TOTAL);
        smem_set = 1;
    }

    int rb = (E + 1 + 255) / 256;
    int items = (M * UNITS) / 8;
    int xb = (items + 255) / 256;

    prep_kernel<<<64, 256>>>(W, (const int*)ec);
    mid_kernel<<<rb + xb, 256>>>(er, E, M, X, rb, items);
    gemm_hmma_kernel<<<(M + 127) / 128, 256, SM_TOTAL>>>(M);
    spmm_kernel<<<(M + 7) / 8, 256>>>(ec, ev, bias, out, M);
}

// round 17
// speedup vs baseline: 1.0672x; 1.0672x over previous
#include <cuda_runtime.h>
#include <cuda_fp16.h>
#include <cstdint>

#define MAX_NODES 100000
#define UNITS 128

// ---------------------------------------------------------------------------
// Scratch (no cudaMalloc allowed)
// ---------------------------------------------------------------------------
__device__ __align__(16) float g_h[(size_t)MAX_NODES * UNITS];       // 51.2 MB
__device__ __align__(16) unsigned short g_xh[(size_t)MAX_NODES * UNITS]; // 25.6 MB fp16 X
__device__ int   g_row_ptr[MAX_NODES + 1];
__device__ int   g_idx64;
// W as fp16, stored as B[n][k] = W[k][n], row-major [128][128]
__device__ __align__(16) unsigned short g_whi[128 * 128];

__device__ __forceinline__ uint32_t smem_u32(const void* p) {
    uint32_t a;
    asm("{ .reg .u64 t; cvta.to.shared.u64 t, %1; cvt.u32.u64 %0, t; }"
        : "=r"(a) : "l"(p));
    return a;
}

__device__ __forceinline__ uint32_t h2_as_u32(__half2 h) {
    union { __half2 h; uint32_t u; } cvt;
    cvt.h = h;
    return cvt.u;
}

template <int IS64>
__device__ __forceinline__ int load_idx(const void* p, int i) {
    if (IS64) return (int)__ldg(((const long long*)p) + i);
    return __ldg(((const int*)p) + i);
}

// ---------------------------------------------------------------------------
// prep: W -> fp16 image B[n][k]  +  index-dtype probe.
// ---------------------------------------------------------------------------
__global__ void prep_kernel(const float* __restrict__ W, const int* __restrict__ ec) {
    if (blockIdx.x == 0 && threadIdx.x == 0) {
        int nz = 0;
        #pragma unroll
        for (int i = 1; i < 64; i += 2) nz += (ec[i] != 0);
        g_idx64 = (nz == 0) ? 1 : 0;
    }
    int i = blockIdx.x * blockDim.x + threadIdx.x;
    if (i >= 128 * 128) return;
    int n = i >> 7, k = i & 127;
    float w = __ldg(W + (size_t)k * 128 + n);
    g_whi[n * 128 + k] = __half_as_ushort(__float2half_rn(w));
}

// ---------------------------------------------------------------------------
// mid: fused  (a) CSR row_ptr edge-diff scatter  (b) X -> fp16 conversion.
// ---------------------------------------------------------------------------
template <int IS64>
__device__ __forceinline__ void rowptr_part(const void* er, int E, int M, int bid) {
    int i = bid * blockDim.x + threadIdx.x;
    if (i > E) return;
    if (i == E) {
        int last = load_idx<IS64>(er, E - 1);
        for (int r = last + 1; r <= M; r++) g_row_ptr[r] = E;
        return;
    }
    int r1 = load_idx<IS64>(er, i);
    int r0 = (i == 0) ? -1 : load_idx<IS64>(er, i - 1);
    for (int r = r0 + 1; r <= r1; r++) g_row_ptr[r] = i;
}

__global__ void mid_kernel(const void* __restrict__ er, int E, int M,
                           const float* __restrict__ X, int rb, int items)
{
    int bid = blockIdx.x;
    if (bid < rb) {
        if (g_idx64) rowptr_part<1>(er, E, M, bid);
        else         rowptr_part<0>(er, E, M, bid);
        return;
    }
    int j = (bid - rb) * blockDim.x + threadIdx.x;
    if (j >= items) return;
    const float4* src = (const float4*)X + (size_t)j * 2;
    float4 a = __ldg(src);
    float4 b = __ldg(src + 1);
    uint4 o;
    o.x = h2_as_u32(__floats2half2_rn(a.x, a.y));
    o.y = h2_as_u32(__floats2half2_rn(a.z, a.w));
    o.z = h2_as_u32(__floats2half2_rn(b.x, b.y));
    o.w = h2_as_u32(__floats2half2_rn(b.z, b.w));
    ((uint4*)g_xh)[j] = o;
}

// ---------------------------------------------------------------------------
// HMMA GEMM: g_h[M,128] = Xh[M,128] @ W[128,128]   (both already fp16)
// cp.async staging, fp32 accum, mma.sync.m16n8k16, 3 CTA/SM.
// ---------------------------------------------------------------------------
#define LDS_STRIDE 136
#define TILE_BYTES (128 * LDS_STRIDE * 2)
#define SM_XHI 0
#define SM_WHI (SM_XHI + TILE_BYTES)
#define SM_TOTAL (SM_WHI + TILE_BYTES)

__device__ __forceinline__ void cp_async16(uint32_t dst, const void* src) {
    asm volatile("cp.async.ca.shared.global [%0], [%1], 16;"
                 :: "r"(dst), "l"(__cvta_generic_to_global(src)) : "memory");
}
__device__ __forceinline__ void cp_async_wait_all() {
    asm volatile("cp.async.commit_group;\n\tcp.async.wait_group 0;" ::: "memory");
}
__device__ __forceinline__ void ldsm_x4(uint32_t* r, uint32_t addr) {
    asm volatile("ldmatrix.sync.aligned.m8n8.x4.shared.b16 {%0,%1,%2,%3}, [%4];"
                 : "=r"(r[0]), "=r"(r[1]), "=r"(r[2]), "=r"(r[3]) : "r"(addr));
}
__device__ __forceinline__ void mma_fp16(float* c, const uint32_t* a, const uint32_t* b) {
    asm volatile(
        "mma.sync.aligned.m16n8k16.row.col.f32.f16.f16.f32 "
        "{%0,%1,%2,%3}, {%4,%5,%6,%7}, {%8,%9}, {%0,%1,%2,%3};"
        : "+f"(c[0]), "+f"(c[1]), "+f"(c[2]), "+f"(c[3])
        : "r"(a[0]), "r"(a[1]), "r"(a[2]), "r"(a[3]), "r"(b[0]), "r"(b[1]));
}

__global__ __launch_bounds__(256, 3)
void gemm_hmma_kernel(int M)
{
    extern __shared__ char smem[];
    const uint32_t sb = smem_u32(smem);
    const int tid = threadIdx.x;
    const int wid = tid >> 5, lane = tid & 31;
    const int m0 = blockIdx.x * 128;
    const int mrows = min(128, M - m0);

    {
        #pragma unroll
        for (int i = 0; i < 8; i++) {
            int cid = tid + i * 256;
            int r = cid >> 4, j = cid & 15;
            if (r < mrows)
                cp_async16(sb + SM_XHI + r * (LDS_STRIDE * 2) + j * 16,
                           g_xh + (size_t)(m0 + r) * 128 + j * 8);
        }
        #pragma unroll
        for (int i = 0; i < 8; i++) {
            int cid = tid + i * 256;
            int r = cid >> 4, j = cid & 15;
            cp_async16(sb + SM_WHI + r * (LDS_STRIDE * 2) + j * 16,
                       g_whi + r * 128 + j * 8);
        }
        if (mrows < 128) {
            for (int cid = tid; cid < 2048; cid += 256) {
                int r = cid >> 4, j = cid & 15;
                if (r >= mrows)
                    *(uint4*)(smem + SM_XHI + r * (LDS_STRIDE * 2) + j * 16) =
                        make_uint4(0, 0, 0, 0);
            }
        }
        cp_async_wait_all();
    }
    __syncthreads();

    const int warp_m = wid & 3, warp_n = wid >> 2;
    const int mb = warp_m * 32;
    const int nb = warp_n * 64;

    float acc[2][8][4];
    #pragma unroll
    for (int i = 0; i < 2; i++)
        #pragma unroll
        for (int j = 0; j < 8; j++)
            #pragma unroll
            for (int q = 0; q < 4; q++) acc[i][j][q] = 0.0f;

    const int g = lane >> 3, lr = lane & 7;

    #pragma unroll
    for (int kk = 0; kk < 8; kk++) {
        const int k0 = kk * 16;
        uint32_t ahi[2][4];
        #pragma unroll
        for (int mt = 0; mt < 2; mt++) {
            uint32_t off = (uint32_t)(mb + mt * 16 + (g & 1) * 8 + lr) * (LDS_STRIDE * 2)
                         + (uint32_t)(k0 + (g >> 1) * 8) * 2;
            ldsm_x4(ahi[mt], sb + SM_XHI + off);
        }
        #pragma unroll
        for (int bt = 0; bt < 4; bt++) {
            uint32_t off = (uint32_t)(nb + bt * 16 + (g >> 1) * 8 + lr) * (LDS_STRIDE * 2)
                         + (uint32_t)(k0 + (g & 1) * 8) * 2;
            uint32_t bhi[4];
            ldsm_x4(bhi, sb + SM_WHI + off);
            #pragma unroll
            for (int mt = 0; mt < 2; mt++)
                #pragma unroll
                for (int nt = 0; nt < 2; nt++)
                    mma_fp16(acc[mt][bt * 2 + nt], ahi[mt], bhi + nt * 2);
        }
    }

    const int er = lane >> 2, ec2 = (lane & 3) * 2;
    #pragma unroll
    for (int mt = 0; mt < 2; mt++) {
        #pragma unroll
        for (int j = 0; j < 8; j++) {
            int n = nb + j * 8 + ec2;
            int m_lo = m0 + mb + mt * 16 + er;
            int m_hi = m_lo + 8;
            if (m_lo < M)
                *(float2*)(g_h + (size_t)m_lo * 128 + n) =
                    make_float2(acc[mt][j][0], acc[mt][j][1]);
            if (m_hi < M)
                *(float2*)(g_h + (size_t)m_hi * 128 + n) =
                    make_float2(acc[mt][j][2], acc[mt][j][3]);
        }
    }
}

// ---------------------------------------------------------------------------
// SpMM + bias + sigmoid. One warp per row, float4 slice per lane. The 8 rows
// of a block own ONE contiguous CSR edge range: stage its ec/ev into smem
// with coalesced loads (few L1tex wavefronts), then the gather loop reads
// them via LDS broadcast — no warp-uniform global loads in the hot loop,
// gathers stay independent (no shfl serialization).
// ---------------------------------------------------------------------------
#define ECHUNK 1024   // edges per staged chunk (8 KB smem)

template <int IS64>
__device__ __forceinline__ void spmm_body(
    const void* ec, const float* ev, const float* bias, float* out, int M)
{
    __shared__ int   sc[ECHUNK];
    __shared__ float sv[ECHUNK];

    int row0 = blockIdx.x * 8;
    int wid = threadIdx.x >> 5, lane = threadIdx.x & 31;
    int row = row0 + wid;
    bool valid = row < M;

    int blk_s = __ldg(&g_row_ptr[row0]);
    int blk_e = __ldg(&g_row_ptr[min(row0 + 8, M)]);
    int s = valid ? __ldg(&g_row_ptr[row]) : 0;
    int e = valid ? __ldg(&g_row_ptr[row + 1]) : 0;

    const float4* hp = (const float4*)g_h;
    float4 acc = make_float4(0, 0, 0, 0);

    for (int cs = blk_s; cs < blk_e; cs += ECHUNK) {
        int ce = min(cs + ECHUNK, blk_e);
        // cooperative coalesced stage of this chunk's ec/ev
        for (int j = cs + threadIdx.x; j < ce; j += 256) {
            sc[j - cs] = load_idx<IS64>(ec, j);
            sv[j - cs] = __ldg(ev + j);
        }
        __syncthreads();

        int ls = max(s, cs), le = min(e, ce);
        int i = ls;
        for (; i + 8 <= le; i += 8) {
            int   c[8];
            float v[8];
            #pragma unroll
            for (int q = 0; q < 8; q++) {
                c[q] = sc[i - cs + q];
                v[q] = sv[i - cs + q];
            }
            float4 h[8];
            #pragma unroll
            for (int q = 0; q < 8; q++) h[q] = hp[(size_t)c[q] * 32 + lane];
            #pragma unroll
            for (int q = 0; q < 8; q++) {
                acc.x = fmaf(v[q], h[q].x, acc.x);
                acc.y = fmaf(v[q], h[q].y, acc.y);
                acc.z = fmaf(v[q], h[q].z, acc.z);
                acc.w = fmaf(v[q], h[q].w, acc.w);
            }
        }
        if (i + 4 <= le) {
            int   c[4];
            float v[4];
            #pragma unroll
            for (int q = 0; q < 4; q++) {
                c[q] = sc[i - cs + q];
                v[q] = sv[i - cs + q];
            }
            float4 h[4];
            #pragma unroll
            for (int q = 0; q < 4; q++) h[q] = hp[(size_t)c[q] * 32 + lane];
            #pragma unroll
            for (int q = 0; q < 4; q++) {
                acc.x = fmaf(v[q], h[q].x, acc.x);
                acc.y = fmaf(v[q], h[q].y, acc.y);
                acc.z = fmaf(v[q], h[q].z, acc.z);
                acc.w = fmaf(v[q], h[q].w, acc.w);
            }
            i += 4;
        }
        for (; i < le; i++) {
            int c0 = sc[i - cs];
            float v0 = sv[i - cs];
            float4 h0 = hp[(size_t)c0 * 32 + lane];
            acc.x = fmaf(v0, h0.x, acc.x); acc.y = fmaf(v0, h0.y, acc.y);
            acc.z = fmaf(v0, h0.z, acc.z); acc.w = fmaf(v0, h0.w, acc.w);
        }
        __syncthreads();
    }

    if (valid) {
        float4 b = __ldg(((const float4*)bias) + lane);
        float4 r;
        r.x = 1.0f / (1.0f + __expf(-(acc.x + b.x)));
        r.y = 1.0f / (1.0f + __expf(-(acc.y + b.y)));
        r.z = 1.0f / (1.0f + __expf(-(acc.z + b.z)));
        r.w = 1.0f / (1.0f + __expf(-(acc.w + b.w)));
        ((float4*)out)[(size_t)row * 32 + lane] = r;
    }
}

__global__ __launch_bounds__(256) void spmm_kernel(
    const void* __restrict__ ec, const float* __restrict__ ev,
    const float* __restrict__ bias, float* __restrict__ out, int M)
{
    if (g_idx64) spmm_body<1>(ec, ev, bias, out, M);
    else         spmm_body<0>(ec, ev, bias, out, M);
}

// ---------------------------------------------------------------------------
// Launch. Inputs: X, edge_row, edge_col, edge_val, weight, bias
// ---------------------------------------------------------------------------
extern "C" void kernel_launch(void* const* d_in, const int* in_sizes, int n_in,
                              void* d_out, int out_size) {
    const float* X    = (const float*)d_in[0];
    const void*  er   = d_in[1];
    const void*  ec   = d_in[2];
    const float* ev   = (const float*)d_in[3];
    const float* W    = (const float*)d_in[4];
    const float* bias = (const float*)d_in[5];
    float* out = (float*)d_out;

    int M = in_sizes[0] / UNITS;     // 100000
    int E = in_sizes[2];             // 1600000

    static int smem_set = 0;
    if (!smem_set) {
        cudaFuncSetAttribute(gemm_hmma_kernel,
                             cudaFuncAttributeMaxDynamicSharedMemorySize, SM_TOTAL);
        smem_set = 1;
    }

    int rb = (E + 1 + 255) / 256;
    int items = (M * UNITS) / 8;
    int xb = (items + 255) / 256;

    prep_kernel<<<64, 256>>>(W, (const int*)ec);
    mid_kernel<<<rb + xb, 256>>>(er, E, M, X, rb, items);
    gemm_hmma_kernel<<<(M + 127) / 128, 256, SM_TOTAL>>>(M);
    spmm_kernel<<<(M + 7) / 8, 256>>>(ec, ev, bias, out, M);
}